// round 3
// baseline (speedup 1.0000x reference)
#include <cuda_runtime.h>
#include <math.h>

namespace {
constexpr int kB  = 64;
constexpr int kSQ = 1024;
constexpr int kSK = 1024;
constexpr int kD  = 256;
constexpr int kDV = 256;

constexpr int BQ = 64;    // q rows per CTA
constexpr int BK = 64;    // keys per chunk
constexpr int NT = 256;   // threads per CTA

constexpr float kScale   = 0.0625f;
constexpr float kDropP   = 0.1f;
constexpr float kKeepInv = 1.0f / 0.9f;

constexpr int SLD = BK + 4;   // 68, Ss row stride

// Qt/Kt: d-major, 64 floats per d-row, XOR-swizzled at float4 granularity.
// float index for element (d, r):
//   d*64 + (((r>>2) ^ ((d>>2)&15)) << 2) + (r&3)
__device__ __forceinline__ int qk_off(int d, int r) {
  return d * 64 + ((((r >> 2) ^ ((d >> 2) & 15)) << 2) | (r & 3));
}

struct Smem {
  float Qt[kD * BQ];    // 65,536 B  (Q^T, swizzled)
  float Kt[kD * BK];    // 65,536 B  (K^T, swizzled)
  float Vs[BK][kDV];    // 65,536 B  (row-major)
  float Ss[BQ][SLD];    // 17,408 B  (post-softmax, post-dropout probs)
  float bias[BK];       //    256 B
};
// total: 214,272 B (< 227 KB limit)
}  // namespace

__global__ __launch_bounds__(NT, 1)
void attn_fp32_kernel(const float* __restrict__ q, const float* __restrict__ k,
                      const float* __restrict__ v, const int* __restrict__ mask,
                      const float* __restrict__ du, float* __restrict__ out) {
  extern __shared__ char smem_raw[];
  Smem* sm = reinterpret_cast<Smem*>(smem_raw);

  const int qt  = blockIdx.x;
  const int b   = blockIdx.y;
  const int tid = threadIdx.x;
  const int tx  = tid & 15;   // 0..15: score-col group / output-col group
  const int ty  = tid >> 4;   // 0..15: row group
  const int q0  = qt * BQ;

  const int r0 = ty * 4;      // this thread's 4 q-rows
  const int c0 = tx * 4;      // this thread's 4 score cols

  // ---- Stage Q transposed+swizzled (coalesced global reads) ----
  {
    const float4* qg = reinterpret_cast<const float4*>(q + (size_t)(b * kSQ + q0) * kD);
    for (int i = tid; i < BQ * kD / 4; i += NT) {
      const int r = i >> 6, c4 = i & 63;
      const float4 x = qg[i];
      const int d = 4 * c4;
      sm->Qt[qk_off(d + 0, r)] = x.x;
      sm->Qt[qk_off(d + 1, r)] = x.y;
      sm->Qt[qk_off(d + 2, r)] = x.z;
      sm->Qt[qk_off(d + 3, r)] = x.w;
    }
  }

  float acc[4][16];   // acc[i][jj*4+e]: out col = 4*tx + 64*jj + e
#pragma unroll
  for (int i = 0; i < 4; i++)
#pragma unroll
    for (int j = 0; j < 16; j++) acc[i][j] = 0.f;

  float mrow[4] = {-INFINITY, -INFINITY, -INFINITY, -INFINITY};
  float lrow[4] = {0.f, 0.f, 0.f, 0.f};

  for (int kt = 0; kt < kSK / BK; ++kt) {
    __syncthreads();  // previous PV done reading Kt/Vs/Ss

    // ---- Stage K chunk (transposed+swizzled), V chunk (row-major), bias ----
    const float4* kg = reinterpret_cast<const float4*>(k + (size_t)(b * kSK + kt * BK) * kD);
    const float4* vg = reinterpret_cast<const float4*>(v + (size_t)(b * kSK + kt * BK) * kDV);
    for (int i = tid; i < BK * kD / 4; i += NT) {
      const int r = i >> 6, c4 = i & 63;
      const float4 x = kg[i];
      const int d = 4 * c4;
      sm->Kt[qk_off(d + 0, r)] = x.x;
      sm->Kt[qk_off(d + 1, r)] = x.y;
      sm->Kt[qk_off(d + 2, r)] = x.z;
      sm->Kt[qk_off(d + 3, r)] = x.w;
    }
    for (int i = tid; i < BK * kDV / 4; i += NT) {
      const int r = i >> 6, c4 = i & 63;
      *reinterpret_cast<float4*>(&sm->Vs[r][c4 * 4]) = vg[i];
    }
    if (tid < BK) {
      const int mv = mask[b * kSK + kt * BK + tid];
      sm->bias[tid] = -1e9f * (1.0f - (float)mv);
    }
    __syncthreads();

    // ---- S = Q K^T : per-thread 4x4 tile, conflict-free fragment loads ----
    float s[4][4];
#pragma unroll
    for (int i = 0; i < 4; i++)
#pragma unroll
      for (int j = 0; j < 4; j++) s[i][j] = 0.f;

#pragma unroll 4
    for (int d = 0; d < kD; ++d) {
      const int sw = (d >> 2) & 15;
      const float4 qv = *reinterpret_cast<const float4*>(&sm->Qt[d * 64 + ((ty ^ sw) << 2)]);
      const float4 kv = *reinterpret_cast<const float4*>(&sm->Kt[d * 64 + ((tx ^ sw) << 2)]);
      const float qa[4] = {qv.x, qv.y, qv.z, qv.w};
      const float ka[4] = {kv.x, kv.y, kv.z, kv.w};
#pragma unroll
      for (int i = 0; i < 4; i++)
#pragma unroll
        for (int j = 0; j < 4; j++) s[i][j] += qa[i] * ka[j];
    }

    // ---- Online softmax update + dropout, per row ----
#pragma unroll
    for (int i = 0; i < 4; i++) {
      float sv[4];
#pragma unroll
      for (int j = 0; j < 4; j++) sv[j] = s[i][j] * kScale + sm->bias[c0 + j];

      float mx = fmaxf(fmaxf(sv[0], sv[1]), fmaxf(sv[2], sv[3]));
#pragma unroll
      for (int off = 8; off >= 1; off >>= 1)
        mx = fmaxf(mx, __shfl_xor_sync(0xffffffffu, mx, off));

      const float mnew = fmaxf(mrow[i], mx);
      const float corr = __expf(mrow[i] - mnew);  // exp(-inf)=0 on first chunk
      mrow[i] = mnew;

      float p[4], rs = 0.f;
#pragma unroll
      for (int j = 0; j < 4; j++) { p[j] = __expf(sv[j] - mnew); rs += p[j]; }
#pragma unroll
      for (int off = 8; off >= 1; off >>= 1)
        rs += __shfl_xor_sync(0xffffffffu, rs, off);

      lrow[i] = lrow[i] * corr + rs;  // normalizer accumulated PRE-dropout (matches ref)

#pragma unroll
      for (int j = 0; j < 16; j++) acc[i][j] *= corr;

      // dropout on the un-normalized numerator
      const float4 u = *reinterpret_cast<const float4*>(
          &du[(size_t)(b * kSQ + q0 + r0 + i) * kSK + kt * BK + c0]);
      p[0] *= (u.x >= kDropP) ? kKeepInv : 0.f;
      p[1] *= (u.y >= kDropP) ? kKeepInv : 0.f;
      p[2] *= (u.z >= kDropP) ? kKeepInv : 0.f;
      p[3] *= (u.w >= kDropP) ? kKeepInv : 0.f;

      *reinterpret_cast<float4*>(&sm->Ss[r0 + i][c0]) = make_float4(p[0], p[1], p[2], p[3]);
    }
    __syncthreads();

    // ---- O += P V : out cols strided (4*tx + 64*jj) => conflict-free V reads ----
#pragma unroll 2
    for (int kk = 0; kk < BK; kk += 4) {
      float4 pr[4];
#pragma unroll
      for (int i = 0; i < 4; i++)
        pr[i] = *reinterpret_cast<const float4*>(&sm->Ss[r0 + i][kk]);
#pragma unroll
      for (int dkk = 0; dkk < 4; dkk++) {
        float4 vv[4];
#pragma unroll
        for (int jj = 0; jj < 4; jj++)
          vv[jj] = *reinterpret_cast<const float4*>(&sm->Vs[kk + dkk][4 * tx + 64 * jj]);
#pragma unroll
        for (int i = 0; i < 4; i++) {
          const float ps = (dkk == 0) ? pr[i].x : (dkk == 1) ? pr[i].y
                          : (dkk == 2) ? pr[i].z : pr[i].w;
#pragma unroll
          for (int jj = 0; jj < 4; jj++) {
            acc[i][jj * 4 + 0] += ps * vv[jj].x;
            acc[i][jj * 4 + 1] += ps * vv[jj].y;
            acc[i][jj * 4 + 2] += ps * vv[jj].z;
            acc[i][jj * 4 + 3] += ps * vv[jj].w;
          }
        }
      }
    }
  }

  // ---- Epilogue: normalize by l and store (coalesced 16B per lane) ----
  float* ob = out + (size_t)(b * kSQ + q0) * kDV;
#pragma unroll
  for (int i = 0; i < 4; i++) {
    const float invl = 1.0f / lrow[i];
#pragma unroll
    for (int jj = 0; jj < 4; jj++) {
      float4 o;
      o.x = acc[i][jj * 4 + 0] * invl;
      o.y = acc[i][jj * 4 + 1] * invl;
      o.z = acc[i][jj * 4 + 2] * invl;
      o.w = acc[i][jj * 4 + 3] * invl;
      *reinterpret_cast<float4*>(ob + (size_t)(r0 + i) * kDV + 4 * tx + 64 * jj) = o;
    }
  }
}

extern "C" void kernel_launch(void* const* d_in, const int* in_sizes, int n_in,
                              void* d_out, int out_size) {
  const float* q    = (const float*)d_in[0];
  const float* k    = (const float*)d_in[1];
  const float* v    = (const float*)d_in[2];
  const int*   mask = (const int*)d_in[3];
  const float* du   = (const float*)d_in[4];
  float* out = (float*)d_out;

  cudaFuncSetAttribute(attn_fp32_kernel,
                       cudaFuncAttributeMaxDynamicSharedMemorySize,
                       (int)sizeof(Smem));

  dim3 grid(kSQ / BQ, kB);  // 16 q-tiles x 64 batches = 1024 CTAs
  attn_fp32_kernel<<<grid, NT, sizeof(Smem)>>>(q, k, v, mask, du, out);
}

// round 5
// speedup vs baseline: 5.5577x; 5.5577x over previous
#include <cuda_runtime.h>
#include <cuda_fp16.h>
#include <stdint.h>

namespace {
constexpr int kB = 64, kSQ = 1024, kSK = 1024, kD = 256, kDV = 256;
constexpr int BQ = 128, BKC = 64, NCH = kSK / BKC, NT = 256;
constexpr float kDropP = 0.1f, kKeepInv = 1.0f / 0.9f;

// smem: rows of 512B (256 fp16), 16B-group XOR swizzle
constexpr uint32_t SM_Q = 0;         // 128 x 512B = 64KB
constexpr uint32_t SM_K = 65536;     // 2 x (64 x 512B) = 64KB
constexpr uint32_t SM_V = 131072;    // 2 x (64 x 512B) = 64KB
constexpr uint32_t SM_BYTES = 196608 + 1024;

__device__ __forceinline__ uint32_t swz(int row, int g) {
  return (uint32_t)(row * 512 + ((g ^ (row & 7)) << 4));
}
__device__ __forceinline__ void cpa16(uint32_t d, const void* s) {
  asm volatile("cp.async.cg.shared.global [%0], [%1], 16;" :: "r"(d), "l"(s));
}
__device__ __forceinline__ void cp_commit() { asm volatile("cp.async.commit_group;" ::: "memory"); }
__device__ __forceinline__ void cp_wait1() { asm volatile("cp.async.wait_group 1;" ::: "memory"); }

__device__ __forceinline__ void ldsm4(uint32_t* r, uint32_t a) {
  asm volatile("ldmatrix.sync.aligned.m8n8.x4.shared.b16 {%0,%1,%2,%3}, [%4];"
               : "=r"(r[0]), "=r"(r[1]), "=r"(r[2]), "=r"(r[3]) : "r"(a));
}
__device__ __forceinline__ void ldsm4t(uint32_t* r, uint32_t a) {
  asm volatile("ldmatrix.sync.aligned.m8n8.x4.trans.shared.b16 {%0,%1,%2,%3}, [%4];"
               : "=r"(r[0]), "=r"(r[1]), "=r"(r[2]), "=r"(r[3]) : "r"(a));
}
__device__ __forceinline__ void mma16816(float* d, const uint32_t* a, const uint32_t* b) {
  asm volatile(
      "mma.sync.aligned.m16n8k16.row.col.f32.f16.f16.f32 "
      "{%0,%1,%2,%3}, {%4,%5,%6,%7}, {%8,%9}, {%0,%1,%2,%3};"
      : "+f"(d[0]), "+f"(d[1]), "+f"(d[2]), "+f"(d[3])
      : "r"(a[0]), "r"(a[1]), "r"(a[2]), "r"(a[3]), "r"(b[0]), "r"(b[1]));
}
}  // namespace

__device__ __half g_Qh[(size_t)kB * kSQ * kD];   // Q * 2^-4
__device__ __half g_Kh[(size_t)kB * kSK * kD];
__device__ __half g_Vh[(size_t)kB * kSK * kDV];  // row-major [k][dv]

__global__ void convert_all(const float* __restrict__ q, const float* __restrict__ k,
                            const float* __restrict__ v) {
  const size_t base = ((size_t)blockIdx.x * blockDim.x + threadIdx.x) * 8;
  if (base >= (size_t)kB * kSQ * kD) return;
  {
    float4 x0 = *reinterpret_cast<const float4*>(q + base);
    float4 x1 = *reinterpret_cast<const float4*>(q + base + 4);
    __half2* o = reinterpret_cast<__half2*>(g_Qh + base);
    o[0] = __floats2half2_rn(x0.x * 0.0625f, x0.y * 0.0625f);
    o[1] = __floats2half2_rn(x0.z * 0.0625f, x0.w * 0.0625f);
    o[2] = __floats2half2_rn(x1.x * 0.0625f, x1.y * 0.0625f);
    o[3] = __floats2half2_rn(x1.z * 0.0625f, x1.w * 0.0625f);
  }
  {
    float4 x0 = *reinterpret_cast<const float4*>(k + base);
    float4 x1 = *reinterpret_cast<const float4*>(k + base + 4);
    __half2* o = reinterpret_cast<__half2*>(g_Kh + base);
    o[0] = __floats2half2_rn(x0.x, x0.y);
    o[1] = __floats2half2_rn(x0.z, x0.w);
    o[2] = __floats2half2_rn(x1.x, x1.y);
    o[3] = __floats2half2_rn(x1.z, x1.w);
  }
  {
    float4 x0 = *reinterpret_cast<const float4*>(v + base);
    float4 x1 = *reinterpret_cast<const float4*>(v + base + 4);
    __half2* o = reinterpret_cast<__half2*>(g_Vh + base);
    o[0] = __floats2half2_rn(x0.x, x0.y);
    o[1] = __floats2half2_rn(x0.z, x0.w);
    o[2] = __floats2half2_rn(x1.x, x1.y);
    o[3] = __floats2half2_rn(x1.z, x1.w);
  }
}

__global__ __launch_bounds__(NT, 1)
void attn_hmma_kernel(const int* __restrict__ mask, const float* __restrict__ du,
                      float* __restrict__ out) {
  extern __shared__ char smraw[];
  uint32_t smb = (uint32_t)__cvta_generic_to_shared(smraw);
  smb = (smb + 1023u) & ~1023u;
  const int tid = threadIdx.x, wid = tid >> 5, lane = tid & 31;
  const int b = blockIdx.y, q0 = blockIdx.x * BQ;

  auto load_q = [&]() {
#pragma unroll
    for (int u = 0; u < 16; u++) {
      const int idx = tid + u * NT, row = idx >> 5, g = idx & 31;
      cpa16(smb + SM_Q + swz(row, g), g_Qh + ((size_t)(b * kSQ + q0 + row)) * kD + g * 8);
    }
  };
  auto load_k = [&](int c, int buf) {
#pragma unroll
    for (int u = 0; u < 8; u++) {
      const int idx = tid + u * NT, row = idx >> 5, g = idx & 31;
      cpa16(smb + SM_K + buf * 32768 + swz(row, g),
            g_Kh + ((size_t)(b * kSK + c * BKC + row)) * kD + g * 8);
    }
  };
  auto load_v = [&](int c, int buf) {
#pragma unroll
    for (int u = 0; u < 8; u++) {
      const int idx = tid + u * NT, row = idx >> 5, g = idx & 31;
      cpa16(smb + SM_V + buf * 32768 + swz(row, g),
            g_Vh + ((size_t)(b * kSK + c * BKC + row)) * kDV + g * 8);
    }
  };

  load_q(); load_k(0, 0); load_v(0, 0); cp_commit();
  load_k(1, 1); load_v(1, 1); cp_commit();

  // fragment lane geometry
  const int rowa = lane >> 2;              // c-frag row 0..7 (and +8)
  const int colq = (lane & 3) * 2;         // c-frag col pair within 8-wide tile
  const int myqrow = wid * 16 + (lane & 15);
  const int qrx = myqrow & 7;
  const uint32_t qrow_base = smb + SM_Q + myqrow * 512;
  const int qg_half = lane >> 4;
  const int krow_off = (lane & 7) + ((lane >> 4) << 3);   // 0..15
  const int kg_half = (lane >> 3) & 1;
  const int vrow_off = lane & 15;
  const int vg_half = lane >> 4;

  const int growa = q0 + wid * 16 + rowa;
  const float* du0 = du + ((size_t)b * kSQ + growa) * kSK;
  const float* du1 = du0 + (size_t)8 * kSK;
  const int* mrow = mask + b * kSK;
  float* out0 = out + ((size_t)b * kSQ + growa) * kDV;
  float* out1 = out0 + (size_t)8 * kDV;

  float o[16][8];
#pragma unroll
  for (int j = 0; j < 16; j++)
#pragma unroll
    for (int e = 0; e < 8; e++) o[j][e] = 0.f;
  float lac0 = 0.f, lac1 = 0.f;

  for (int kt = 0; kt < NCH; kt++) {
    cp_wait1();
    __syncthreads();
    const uint32_t kbuf = smb + SM_K + (kt & 1) * 32768;
    const uint32_t vbuf = smb + SM_V + (kt & 1) * 32768;

    // ---- S = Q K^T : per-warp 16x64, HMMA ----
    float s[8][4];
#pragma unroll
    for (int t = 0; t < 8; t++) { s[t][0] = s[t][1] = s[t][2] = s[t][3] = 0.f; }

#pragma unroll
    for (int ds = 0; ds < 16; ds++) {
      uint32_t a[4];
      ldsm4(a, qrow_base + ((((ds << 1) + qg_half) ^ qrx) << 4));
#pragma unroll
      for (int j = 0; j < 4; j++) {
        const int key = j * 16 + krow_off;
        uint32_t bb[4];
        ldsm4(bb, kbuf + key * 512 + ((((ds << 1) + kg_half) ^ (key & 7)) << 4));
        mma16816(s[2 * j], a, bb + 0);
        mma16816(s[2 * j + 1], a, bb + 2);
      }
    }

    // ---- mask + exp + dropout, S c-frag -> P a-frag in registers ----
    uint32_t pa[8], pb[8];
    const int kc0 = kt * BKC;
#pragma unroll
    for (int t = 0; t < 8; t++) {
      const int kc = kc0 + t * 8 + colq;
      const int2 mm = *reinterpret_cast<const int2*>(mrow + kc);
      const float2 u0 = *reinterpret_cast<const float2*>(du0 + kc);
      const float2 u1 = *reinterpret_cast<const float2*>(du1 + kc);
      float p0 = mm.x ? __expf(s[t][0]) : 0.f;
      float p1 = mm.y ? __expf(s[t][1]) : 0.f;
      float p2 = mm.x ? __expf(s[t][2]) : 0.f;
      float p3 = mm.y ? __expf(s[t][3]) : 0.f;
      lac0 += p0 + p1;
      lac1 += p2 + p3;
      p0 *= (u0.x >= kDropP) ? kKeepInv : 0.f;
      p1 *= (u0.y >= kDropP) ? kKeepInv : 0.f;
      p2 *= (u1.x >= kDropP) ? kKeepInv : 0.f;
      p3 *= (u1.y >= kDropP) ? kKeepInv : 0.f;
      __half2 ha = __floats2half2_rn(p0, p1), hb = __floats2half2_rn(p2, p3);
      pa[t] = *reinterpret_cast<uint32_t*>(&ha);
      pb[t] = *reinterpret_cast<uint32_t*>(&hb);
    }

    // ---- O += P V ----
#pragma unroll
    for (int ks = 0; ks < 4; ks++) {
      uint32_t a2[4] = {pa[2 * ks], pb[2 * ks], pa[2 * ks + 1], pb[2 * ks + 1]};
      const int key = ks * 16 + vrow_off;
      const uint32_t rowb = vbuf + key * 512;
      const int kx = key & 7;
#pragma unroll
      for (int j = 0; j < 16; j++) {
        uint32_t bb[4];
        ldsm4t(bb, rowb + ((((j << 1) + vg_half) ^ kx) << 4));
        mma16816(o[j] + 0, a2, bb + 0);
        mma16816(o[j] + 4, a2, bb + 2);
      }
    }

    __syncthreads();  // all warps done reading this chunk's buffers
    if (kt + 2 < NCH) { load_k(kt + 2, kt & 1); load_v(kt + 2, kt & 1); }
    cp_commit();
  }

  // ---- l reduction over quad (cols live in lane&3) ----
  lac0 += __shfl_xor_sync(0xffffffffu, lac0, 1);
  lac0 += __shfl_xor_sync(0xffffffffu, lac0, 2);
  lac1 += __shfl_xor_sync(0xffffffffu, lac1, 1);
  lac1 += __shfl_xor_sync(0xffffffffu, lac1, 2);
  const float inv0 = 1.0f / lac0, inv1 = 1.0f / lac1;

#pragma unroll
  for (int j = 0; j < 16; j++) {
#pragma unroll
    for (int sd = 0; sd < 2; sd++) {
      const int c = j * 16 + sd * 8 + colq;
      float2 w0, w1;
      w0.x = o[j][sd * 4 + 0] * inv0;
      w0.y = o[j][sd * 4 + 1] * inv0;
      w1.x = o[j][sd * 4 + 2] * inv1;
      w1.y = o[j][sd * 4 + 3] * inv1;
      *reinterpret_cast<float2*>(out0 + c) = w0;
      *reinterpret_cast<float2*>(out1 + c) = w1;
    }
  }
}

extern "C" void kernel_launch(void* const* d_in, const int* in_sizes, int n_in,
                              void* d_out, int out_size) {
  const float* q = (const float*)d_in[0];
  const float* k = (const float*)d_in[1];
  const float* v = (const float*)d_in[2];
  const int* mask = (const int*)d_in[3];
  const float* du = (const float*)d_in[4];
  float* out = (float*)d_out;

  convert_all<<<(int)(((size_t)kB * kSQ * kD / 8 + 255) / 256), 256>>>(q, k, v);

  cudaFuncSetAttribute(attn_hmma_kernel, cudaFuncAttributeMaxDynamicSharedMemorySize,
                       (int)SM_BYTES);
  attn_hmma_kernel<<<dim3(kSQ / BQ, kB), NT, SM_BYTES>>>(mask, du, out);
}

// round 6
// speedup vs baseline: 6.2180x; 1.1188x over previous
#include <cuda_runtime.h>
#include <cuda_fp16.h>
#include <stdint.h>

namespace {
constexpr int kB = 64, kSQ = 1024, kSK = 1024, kD = 256, kDV = 256;
constexpr int BQ = 128, BKC = 64, NCH = kSK / BKC, NT = 512;
constexpr float kDropP = 0.1f, kKeepInv = 1.0f / 0.9f;

// Q/K/V rows: 512B (256 fp16), 32 16B-groups, XOR swizzle
constexpr uint32_t SM_Q = 0;         // 128 x 512B = 64KB
constexpr uint32_t SM_K = 65536;     // 2 x (64 x 512B) = 64KB
constexpr uint32_t SM_V = 131072;    // 2 x (64 x 512B) = 64KB
constexpr uint32_t SM_P = 196608;    // 128 rows x 128B (64 fp16) = 16KB
constexpr uint32_t SM_L = 212992;    // float[2][128] = 1KB
constexpr uint32_t SM_BYTES = 214016 + 1024;

__device__ __forceinline__ uint32_t swz(int row, int g) {          // 512B rows
  return (uint32_t)(row * 512 + ((g ^ (row & 7)) << 4));
}
__device__ __forceinline__ void cpa16(uint32_t d, const void* s) {
  asm volatile("cp.async.cg.shared.global [%0], [%1], 16;" :: "r"(d), "l"(s));
}
__device__ __forceinline__ void cp_commit() { asm volatile("cp.async.commit_group;" ::: "memory"); }
__device__ __forceinline__ void cp_wait2() { asm volatile("cp.async.wait_group 2;" ::: "memory"); }

__device__ __forceinline__ void ldsm4(uint32_t* r, uint32_t a) {
  asm volatile("ldmatrix.sync.aligned.m8n8.x4.shared.b16 {%0,%1,%2,%3}, [%4];"
               : "=r"(r[0]), "=r"(r[1]), "=r"(r[2]), "=r"(r[3]) : "r"(a));
}
__device__ __forceinline__ void ldsm4t(uint32_t* r, uint32_t a) {
  asm volatile("ldmatrix.sync.aligned.m8n8.x4.trans.shared.b16 {%0,%1,%2,%3}, [%4];"
               : "=r"(r[0]), "=r"(r[1]), "=r"(r[2]), "=r"(r[3]) : "r"(a));
}
__device__ __forceinline__ void mma16816(float* d, const uint32_t* a, const uint32_t* b) {
  asm volatile(
      "mma.sync.aligned.m16n8k16.row.col.f32.f16.f16.f32 "
      "{%0,%1,%2,%3}, {%4,%5,%6,%7}, {%8,%9}, {%0,%1,%2,%3};"
      : "+f"(d[0]), "+f"(d[1]), "+f"(d[2]), "+f"(d[3])
      : "r"(a[0]), "r"(a[1]), "r"(a[2]), "r"(a[3]), "r"(b[0]), "r"(b[1]));
}
}  // namespace

__device__ __half g_Qh[(size_t)kB * kSQ * kD];   // Q * 2^-4
__device__ __half g_Kh[(size_t)kB * kSK * kD];
__device__ __half g_Vh[(size_t)kB * kSK * kDV];

__global__ void convert_all(const float* __restrict__ q, const float* __restrict__ k,
                            const float* __restrict__ v) {
  const size_t base = ((size_t)blockIdx.x * blockDim.x + threadIdx.x) * 8;
  if (base >= (size_t)kB * kSQ * kD) return;
  {
    float4 x0 = *reinterpret_cast<const float4*>(q + base);
    float4 x1 = *reinterpret_cast<const float4*>(q + base + 4);
    __half2* o = reinterpret_cast<__half2*>(g_Qh + base);
    o[0] = __floats2half2_rn(x0.x * 0.0625f, x0.y * 0.0625f);
    o[1] = __floats2half2_rn(x0.z * 0.0625f, x0.w * 0.0625f);
    o[2] = __floats2half2_rn(x1.x * 0.0625f, x1.y * 0.0625f);
    o[3] = __floats2half2_rn(x1.z * 0.0625f, x1.w * 0.0625f);
  }
  {
    float4 x0 = *reinterpret_cast<const float4*>(k + base);
    float4 x1 = *reinterpret_cast<const float4*>(k + base + 4);
    __half2* o = reinterpret_cast<__half2*>(g_Kh + base);
    o[0] = __floats2half2_rn(x0.x, x0.y);
    o[1] = __floats2half2_rn(x0.z, x0.w);
    o[2] = __floats2half2_rn(x1.x, x1.y);
    o[3] = __floats2half2_rn(x1.z, x1.w);
  }
  {
    float4 x0 = *reinterpret_cast<const float4*>(v + base);
    float4 x1 = *reinterpret_cast<const float4*>(v + base + 4);
    __half2* o = reinterpret_cast<__half2*>(g_Vh + base);
    o[0] = __floats2half2_rn(x0.x, x0.y);
    o[1] = __floats2half2_rn(x0.z, x0.w);
    o[2] = __floats2half2_rn(x1.x, x1.y);
    o[3] = __floats2half2_rn(x1.z, x1.w);
  }
}

__global__ __launch_bounds__(NT, 1)
void attn_hmma_kernel(const int* __restrict__ mask, const float* __restrict__ du,
                      float* __restrict__ out) {
  extern __shared__ char smraw[];
  uint32_t smb = (uint32_t)__cvta_generic_to_shared(smraw);
  smb = (smb + 1023u) & ~1023u;
  const int tid = threadIdx.x, wid = tid >> 5, lane = tid & 31;
  const int b = blockIdx.y, q0 = blockIdx.x * BQ;
  const int g = wid & 7;        // row group: q-rows g*16..g*16+15
  const int kh = wid >> 3;      // QK: key half (32 keys); PV: dv half (128 cols)

  auto load_q = [&]() {
#pragma unroll
    for (int u = 0; u < 8; u++) {
      const int idx = tid + u * NT, row = idx >> 5, gr = idx & 31;
      cpa16(smb + SM_Q + swz(row, gr), g_Qh + ((size_t)(b * kSQ + q0 + row)) * kD + gr * 8);
    }
  };
  auto load_k = [&](int c, int buf) {
#pragma unroll
    for (int u = 0; u < 4; u++) {
      const int idx = tid + u * NT, row = idx >> 5, gr = idx & 31;
      cpa16(smb + SM_K + buf * 32768 + swz(row, gr),
            g_Kh + ((size_t)(b * kSK + c * BKC + row)) * kD + gr * 8);
    }
  };
  auto load_v = [&](int c, int buf) {
#pragma unroll
    for (int u = 0; u < 4; u++) {
      const int idx = tid + u * NT, row = idx >> 5, gr = idx & 31;
      cpa16(smb + SM_V + buf * 32768 + swz(row, gr),
            g_Vh + ((size_t)(b * kSK + c * BKC + row)) * kDV + gr * 8);
    }
  };

  load_q(); load_k(0, 0); load_v(0, 0); cp_commit();  // G1
  load_k(1, 1); cp_commit();                          // G2
  load_v(1, 1); cp_commit();                          // G3

  // lane geometry
  const int lq = lane & 15, lhalf = lane >> 4;
  const int rowa = lane >> 2, colq = (lane & 3) * 2;
  const int r0l = g * 16 + rowa;          // local row (and +8)
  const int qrow = g * 16 + lq;
  const int qrx = qrow & 7;
  const uint32_t qbase = smb + SM_Q + qrow * 512;
  const int krow_off = (lane & 7) + ((lane >> 4) << 3);
  const int kg_half = (lane >> 3) & 1;
  const int prow = g * 16 + lq;
  const uint32_t pbase = smb + SM_P + prow * 128;
  const int prx = prow & 7;

  const int grow0 = q0 + r0l;
  const float* du0 = du + ((size_t)b * kSQ + grow0) * kSK;
  const float* du1 = du0 + (size_t)8 * kSK;
  const int* mrow = mask + b * kSK;

  float o[8][8];
#pragma unroll
  for (int j = 0; j < 8; j++)
#pragma unroll
    for (int e = 0; e < 8; e++) o[j][e] = 0.f;
  float lac0 = 0.f, lac1 = 0.f;

  for (int kt = 0; kt < NCH; kt++) {
    cp_wait2();
    __syncthreads();  // K/V(kt) resident; P(kt-1) fully consumed
    const uint32_t kbuf = smb + SM_K + (kt & 1) * 32768;
    const uint32_t vbuf = smb + SM_V + (kt & 1) * 32768;

    // ---- QK: this warp's 16 rows x 32 keys (keys kh*32..) ----
    float s[4][4];
#pragma unroll
    for (int t = 0; t < 4; t++) { s[t][0] = s[t][1] = s[t][2] = s[t][3] = 0.f; }
#pragma unroll
    for (int ds = 0; ds < 16; ds++) {
      uint32_t a[4];
      ldsm4(a, qbase + ((((ds << 1) + lhalf) ^ qrx) << 4));
#pragma unroll
      for (int j = 0; j < 2; j++) {
        const int key = kh * 32 + j * 16 + krow_off;
        uint32_t bb[4];
        ldsm4(bb, kbuf + key * 512 + ((((ds << 1) + kg_half) ^ (key & 7)) << 4));
        mma16816(s[2 * j], a, bb + 0);
        mma16816(s[2 * j + 1], a, bb + 2);
      }
    }

    // ---- mask/exp/dropout; write P (fp16) to smem ----
    const int kc0 = kt * BKC + kh * 32;
#pragma unroll
    for (int t = 0; t < 4; t++) {
      const int kc = kc0 + t * 8 + colq;
      const int2 mm = *reinterpret_cast<const int2*>(mrow + kc);
      const float2 u0 = *reinterpret_cast<const float2*>(du0 + kc);
      const float2 u1 = *reinterpret_cast<const float2*>(du1 + kc);
      float p0 = mm.x ? __expf(s[t][0]) : 0.f;
      float p1 = mm.y ? __expf(s[t][1]) : 0.f;
      float p2 = mm.x ? __expf(s[t][2]) : 0.f;
      float p3 = mm.y ? __expf(s[t][3]) : 0.f;
      lac0 += p0 + p1;
      lac1 += p2 + p3;
      p0 *= (u0.x >= kDropP) ? kKeepInv : 0.f;
      p1 *= (u0.y >= kDropP) ? kKeepInv : 0.f;
      p2 *= (u1.x >= kDropP) ? kKeepInv : 0.f;
      p3 *= (u1.y >= kDropP) ? kKeepInv : 0.f;
      __half2 ha = __floats2half2_rn(p0, p1), hb = __floats2half2_rn(p2, p3);
      const int grp = kh * 4 + t;                 // 16B group within 128B P row
      const uint32_t a0 = smb + SM_P + (r0l)     * 128 + ((grp ^ (r0l & 7))       << 4) + (lane & 3) * 4;
      const uint32_t a1 = smb + SM_P + (r0l + 8) * 128 + ((grp ^ ((r0l + 8) & 7)) << 4) + (lane & 3) * 4;
      asm volatile("st.shared.b32 [%0], %1;" :: "r"(a0), "r"(*reinterpret_cast<uint32_t*>(&ha)) : "memory");
      asm volatile("st.shared.b32 [%0], %1;" :: "r"(a1), "r"(*reinterpret_cast<uint32_t*>(&hb)) : "memory");
    }
    __syncthreads();  // P(kt) visible; K-buf free (QK done)

    if (kt + 2 < NCH) load_k(kt + 2, kt & 1);
    cp_commit();

    // ---- PV: this warp's 16 rows x 128 dv (cols kh*128..) ----
#pragma unroll
    for (int ks = 0; ks < 4; ks++) {
      uint32_t a2[4];
      ldsm4(a2, pbase + ((((ks << 1) + lhalf) ^ prx) << 4));
      const int key = ks * 16 + lq;
      const uint32_t rowb = vbuf + key * 512;
      const int kx = key & 7;
#pragma unroll
      for (int jt = 0; jt < 8; jt++) {
        uint32_t bb[4];
        ldsm4t(bb, rowb + ((((kh << 4) + (jt << 1) + lhalf) ^ kx) << 4));
        mma16816(o[jt] + 0, a2, bb + 0);
        mma16816(o[jt] + 4, a2, bb + 2);
      }
    }
    __syncthreads();  // V-buf free

    if (kt + 2 < NCH) load_v(kt + 2, kt & 1);
    cp_commit();
  }

  // ---- combine l across key-halves via smem ----
  lac0 += __shfl_xor_sync(0xffffffffu, lac0, 1);
  lac0 += __shfl_xor_sync(0xffffffffu, lac0, 2);
  lac1 += __shfl_xor_sync(0xffffffffu, lac1, 1);
  lac1 += __shfl_xor_sync(0xffffffffu, lac1, 2);
  if ((lane & 3) == 0) {
    asm volatile("st.shared.f32 [%0], %1;" :: "r"(smb + SM_L + (kh * 128 + r0l) * 4), "f"(lac0) : "memory");
    asm volatile("st.shared.f32 [%0], %1;" :: "r"(smb + SM_L + (kh * 128 + r0l + 8) * 4), "f"(lac1) : "memory");
  }
  __syncthreads();
  float la0, lb0, la1, lb1;
  asm volatile("ld.shared.f32 %0, [%1];" : "=f"(la0) : "r"(smb + SM_L + r0l * 4));
  asm volatile("ld.shared.f32 %0, [%1];" : "=f"(lb0) : "r"(smb + SM_L + (128 + r0l) * 4));
  asm volatile("ld.shared.f32 %0, [%1];" : "=f"(la1) : "r"(smb + SM_L + (r0l + 8) * 4));
  asm volatile("ld.shared.f32 %0, [%1];" : "=f"(lb1) : "r"(smb + SM_L + (128 + r0l + 8) * 4));
  const float inv0 = 1.0f / (la0 + lb0), inv1 = 1.0f / (la1 + lb1);

  float* out0 = out + ((size_t)b * kSQ + grow0) * kDV + kh * 128;
  float* out1 = out0 + (size_t)8 * kDV;
#pragma unroll
  for (int jt = 0; jt < 8; jt++) {
#pragma unroll
    for (int sd = 0; sd < 2; sd++) {
      const int c = jt * 16 + sd * 8 + colq;
      float2 w0, w1;
      w0.x = o[jt][sd * 4 + 0] * inv0;
      w0.y = o[jt][sd * 4 + 1] * inv0;
      w1.x = o[jt][sd * 4 + 2] * inv1;
      w1.y = o[jt][sd * 4 + 3] * inv1;
      *reinterpret_cast<float2*>(out0 + c) = w0;
      *reinterpret_cast<float2*>(out1 + c) = w1;
    }
  }
}

extern "C" void kernel_launch(void* const* d_in, const int* in_sizes, int n_in,
                              void* d_out, int out_size) {
  const float* q = (const float*)d_in[0];
  const float* k = (const float*)d_in[1];
  const float* v = (const float*)d_in[2];
  const int* mask = (const int*)d_in[3];
  const float* du = (const float*)d_in[4];
  float* out = (float*)d_out;

  convert_all<<<(int)(((size_t)kB * kSQ * kD / 8 + 255) / 256), 256>>>(q, k, v);

  cudaFuncSetAttribute(attn_hmma_kernel, cudaFuncAttributeMaxDynamicSharedMemorySize,
                       (int)SM_BYTES);
  attn_hmma_kernel<<<dim3(kSQ / BQ, kB), NT, SM_BYTES>>>(mask, du, out);
}

// round 7
// speedup vs baseline: 6.6000x; 1.0614x over previous
#include <cuda_runtime.h>
#include <cuda_fp16.h>
#include <stdint.h>

namespace {
constexpr int kB = 64, kSQ = 1024, kSK = 1024, kD = 256, kDV = 256;
constexpr int BQ = 128, BKC = 64, NCH = kSK / BKC, NT = 512;
constexpr float kDropP = 0.1f, kKeepInv = 1.0f / 0.9f;

constexpr uint32_t SM_Q = 0;         // 128 x 512B = 64KB
constexpr uint32_t SM_K = 65536;     // 2 x (64 x 512B) = 64KB
constexpr uint32_t SM_V = 131072;    // 2 x (64 x 512B) = 64KB
constexpr uint32_t SM_P = 196608;    // 128 rows x 128B = 16KB
constexpr uint32_t SM_L = 212992;    // float[2][128] = 1KB
constexpr uint32_t SM_BYTES = 214016 + 1024;

__device__ __forceinline__ uint32_t swz(int row, int g) {  // 512B rows
  return (uint32_t)(row * 512 + ((g ^ (row & 7)) << 4));
}
__device__ __forceinline__ void cpa16(uint32_t d, const void* s) {
  asm volatile("cp.async.cg.shared.global [%0], [%1], 16;" :: "r"(d), "l"(s));
}
__device__ __forceinline__ void cp_commit() { asm volatile("cp.async.commit_group;" ::: "memory"); }
__device__ __forceinline__ void cp_wait2() { asm volatile("cp.async.wait_group 2;" ::: "memory"); }

__device__ __forceinline__ void ldsm4(uint32_t* r, uint32_t a) {
  asm volatile("ldmatrix.sync.aligned.m8n8.x4.shared.b16 {%0,%1,%2,%3}, [%4];"
               : "=r"(r[0]), "=r"(r[1]), "=r"(r[2]), "=r"(r[3]) : "r"(a));
}
__device__ __forceinline__ void ldsm4t(uint32_t* r, uint32_t a) {
  asm volatile("ldmatrix.sync.aligned.m8n8.x4.trans.shared.b16 {%0,%1,%2,%3}, [%4];"
               : "=r"(r[0]), "=r"(r[1]), "=r"(r[2]), "=r"(r[3]) : "r"(a));
}
__device__ __forceinline__ void mma16816(float* d, const uint32_t* a, const uint32_t* b) {
  asm volatile(
      "mma.sync.aligned.m16n8k16.row.col.f32.f16.f16.f32 "
      "{%0,%1,%2,%3}, {%4,%5,%6,%7}, {%8,%9}, {%0,%1,%2,%3};"
      : "+f"(d[0]), "+f"(d[1]), "+f"(d[2]), "+f"(d[3])
      : "r"(a[0]), "r"(a[1]), "r"(a[2]), "r"(a[3]), "r"(b[0]), "r"(b[1]));
}
}  // namespace

__device__ __half g_Qh[(size_t)kB * kSQ * kD];   // Q * 2^-4
__device__ __half g_Kh[(size_t)kB * kSK * kD];
__device__ __half g_Vh[(size_t)kB * kSK * kDV];
__device__ uint32_t g_dropbits[(size_t)kB * kSQ * (kSK / 32)];  // 8MB
__device__ uint32_t g_maskbits[kB * (kSK / 32)];                // 8KB

__global__ void convert_all(const float* __restrict__ q, const float* __restrict__ k,
                            const float* __restrict__ v) {
  const size_t base = ((size_t)blockIdx.x * blockDim.x + threadIdx.x) * 8;
  if (base >= (size_t)kB * kSQ * kD) return;
  {
    float4 x0 = *reinterpret_cast<const float4*>(q + base);
    float4 x1 = *reinterpret_cast<const float4*>(q + base + 4);
    __half2* o = reinterpret_cast<__half2*>(g_Qh + base);
    o[0] = __floats2half2_rn(x0.x * 0.0625f, x0.y * 0.0625f);
    o[1] = __floats2half2_rn(x0.z * 0.0625f, x0.w * 0.0625f);
    o[2] = __floats2half2_rn(x1.x * 0.0625f, x1.y * 0.0625f);
    o[3] = __floats2half2_rn(x1.z * 0.0625f, x1.w * 0.0625f);
  }
  {
    float4 x0 = *reinterpret_cast<const float4*>(k + base);
    float4 x1 = *reinterpret_cast<const float4*>(k + base + 4);
    __half2* o = reinterpret_cast<__half2*>(g_Kh + base);
    o[0] = __floats2half2_rn(x0.x, x0.y);
    o[1] = __floats2half2_rn(x0.z, x0.w);
    o[2] = __floats2half2_rn(x1.x, x1.y);
    o[3] = __floats2half2_rn(x1.z, x1.w);
  }
  {
    float4 x0 = *reinterpret_cast<const float4*>(v + base);
    float4 x1 = *reinterpret_cast<const float4*>(v + base + 4);
    __half2* o = reinterpret_cast<__half2*>(g_Vh + base);
    o[0] = __floats2half2_rn(x0.x, x0.y);
    o[1] = __floats2half2_rn(x0.z, x0.w);
    o[2] = __floats2half2_rn(x1.x, x1.y);
    o[3] = __floats2half2_rn(x1.z, x1.w);
  }
}

__global__ void make_dropbits(const float* __restrict__ du) {
  const int lane = threadIdx.x & 31;
  const size_t warp = (((size_t)blockIdx.x * blockDim.x) + threadIdx.x) >> 5;
  const size_t base = warp * 1024;
  uint32_t myword = 0;
#pragma unroll
  for (int i = 0; i < 32; i++) {
    const float u = du[base + (size_t)i * 32 + lane];
    const uint32_t bm = __ballot_sync(0xffffffffu, u >= kDropP);
    if (lane == i) myword = bm;
  }
  g_dropbits[warp * 32 + lane] = myword;
}

__global__ void make_maskbits(const int* __restrict__ mask) {
  const int lane = threadIdx.x & 31;
  const int warp = (int)((blockIdx.x * blockDim.x + threadIdx.x) >> 5);
  const size_t base = (size_t)warp * 1024;
  uint32_t myword = 0;
#pragma unroll
  for (int i = 0; i < 32; i++) {
    const int m = mask[base + (size_t)i * 32 + lane];
    const uint32_t bm = __ballot_sync(0xffffffffu, m != 0);
    if (lane == i) myword = bm;
  }
  g_maskbits[warp * 32 + lane] = myword;
}

__global__ __launch_bounds__(NT, 1)
void attn_hmma_kernel(float* __restrict__ out) {
  extern __shared__ char smraw[];
  uint32_t smb = (uint32_t)__cvta_generic_to_shared(smraw);
  smb = (smb + 1023u) & ~1023u;
  const int tid = threadIdx.x, wid = tid >> 5, lane = tid & 31;
  const int b = blockIdx.y, q0 = blockIdx.x * BQ;
  const int g = wid & 7;    // QK row group (16 rows)
  const int kh = wid >> 3;  // QK key half (32 keys)
  const int pr = wid >> 2;  // PV row group (32 rows)
  const int pg = wid & 3;   // PV col group (64 cols)

  auto load_q = [&]() {
#pragma unroll
    for (int u = 0; u < 8; u++) {
      const int idx = tid + u * NT, row = idx >> 5, gr = idx & 31;
      cpa16(smb + SM_Q + swz(row, gr), g_Qh + ((size_t)(b * kSQ + q0 + row)) * kD + gr * 8);
    }
  };
  auto load_k = [&](int c, int buf) {
#pragma unroll
    for (int u = 0; u < 4; u++) {
      const int idx = tid + u * NT, row = idx >> 5, gr = idx & 31;
      cpa16(smb + SM_K + buf * 32768 + swz(row, gr),
            g_Kh + ((size_t)(b * kSK + c * BKC + row)) * kD + gr * 8);
    }
  };
  auto load_v = [&](int c, int buf) {
#pragma unroll
    for (int u = 0; u < 4; u++) {
      const int idx = tid + u * NT, row = idx >> 5, gr = idx & 31;
      cpa16(smb + SM_V + buf * 32768 + swz(row, gr),
            g_Vh + ((size_t)(b * kSK + c * BKC + row)) * kDV + gr * 8);
    }
  };

  load_q(); load_k(0, 0); load_v(0, 0); cp_commit();  // G1
  load_k(1, 1); cp_commit();                          // G2
  load_v(1, 1); cp_commit();                          // G3

  // lane geometry
  const int lq = lane & 15, lhalf = lane >> 4;
  const int rowa = lane >> 2, colq = (lane & 3) * 2;
  const int r0l = g * 16 + rowa;
  const int qrow = g * 16 + lq;
  const int qrx = qrow & 7;
  const uint32_t qbase = smb + SM_Q + qrow * 512;
  const int krow_off = (lane & 7) + ((lane >> 4) << 3);
  const int kg_half = (lane >> 3) & 1;

  const int grow0 = q0 + r0l;

  float o[2][8][4];
#pragma unroll
  for (int mt = 0; mt < 2; mt++)
#pragma unroll
    for (int nt = 0; nt < 8; nt++)
#pragma unroll
      for (int e = 0; e < 4; e++) o[mt][nt][e] = 0.f;
  float lac0 = 0.f, lac1 = 0.f;

  for (int kt = 0; kt < NCH; kt++) {
    cp_wait2();
    __syncthreads();  // K/V(kt) resident; P(kt-1) consumed
    const uint32_t kbuf = smb + SM_K + (kt & 1) * 32768;
    const uint32_t vbuf = smb + SM_V + (kt & 1) * 32768;

    // hoisted bit-word loads (hidden under QK MMAs)
    const int wix = kt * 2 + kh;
    const uint32_t mword = g_maskbits[b * 32 + wix];
    const uint32_t dw0 = g_dropbits[(size_t)(b * kSQ + grow0) * 32 + wix];
    const uint32_t dw1 = g_dropbits[(size_t)(b * kSQ + grow0 + 8) * 32 + wix];

    // ---- QK: 16 rows x 32 keys per warp ----
    float s[4][4];
#pragma unroll
    for (int t = 0; t < 4; t++) { s[t][0] = s[t][1] = s[t][2] = s[t][3] = 0.f; }
#pragma unroll
    for (int ds = 0; ds < 16; ds++) {
      uint32_t a[4];
      ldsm4(a, qbase + ((((ds << 1) + lhalf) ^ qrx) << 4));
#pragma unroll
      for (int j = 0; j < 2; j++) {
        const int key = kh * 32 + j * 16 + krow_off;
        uint32_t bb[4];
        ldsm4(bb, kbuf + key * 512 + ((((ds << 1) + kg_half) ^ (key & 7)) << 4));
        mma16816(s[2 * j], a, bb + 0);
        mma16816(s[2 * j + 1], a, bb + 2);
      }
    }

    // ---- mask/exp/dropout via bitwords; write P fp16 to smem ----
#pragma unroll
    for (int t = 0; t < 4; t++) {
      const int bp = t * 8 + colq;
      const bool m0 = (mword >> bp) & 1u, m1 = (mword >> (bp + 1)) & 1u;
      float p0 = m0 ? __expf(s[t][0]) : 0.f;
      float p1 = m1 ? __expf(s[t][1]) : 0.f;
      float p2 = m0 ? __expf(s[t][2]) : 0.f;
      float p3 = m1 ? __expf(s[t][3]) : 0.f;
      lac0 += p0 + p1;
      lac1 += p2 + p3;
      p0 *= ((dw0 >> bp) & 1u) ? kKeepInv : 0.f;
      p1 *= ((dw0 >> (bp + 1)) & 1u) ? kKeepInv : 0.f;
      p2 *= ((dw1 >> bp) & 1u) ? kKeepInv : 0.f;
      p3 *= ((dw1 >> (bp + 1)) & 1u) ? kKeepInv : 0.f;
      __half2 ha = __floats2half2_rn(p0, p1), hb = __floats2half2_rn(p2, p3);
      const int grp = kh * 4 + t;
      const uint32_t a0 = smb + SM_P + (r0l)     * 128 + ((grp ^ (r0l & 7))       << 4) + (lane & 3) * 4;
      const uint32_t a1 = smb + SM_P + (r0l + 8) * 128 + ((grp ^ ((r0l + 8) & 7)) << 4) + (lane & 3) * 4;
      asm volatile("st.shared.b32 [%0], %1;" :: "r"(a0), "r"(*reinterpret_cast<uint32_t*>(&ha)) : "memory");
      asm volatile("st.shared.b32 [%0], %1;" :: "r"(a1), "r"(*reinterpret_cast<uint32_t*>(&hb)) : "memory");
    }
    __syncthreads();  // P(kt) visible; K-buf free

    if (kt + 2 < NCH) load_k(kt + 2, kt & 1);
    cp_commit();

    // ---- PV: 32 rows x 64 dv per warp (pr, pg) ----
#pragma unroll
    for (int ks = 0; ks < 4; ks++) {
      uint32_t ap[2][4];
#pragma unroll
      for (int mt = 0; mt < 2; mt++) {
        const int prow2 = pr * 32 + mt * 16 + lq;
        ldsm4(ap[mt], smb + SM_P + prow2 * 128 + ((((ks << 1) + lhalf) ^ (prow2 & 7)) << 4));
      }
      const int key = ks * 16 + lq;
      const uint32_t rowb = vbuf + key * 512;
      const int kx = key & 7;
#pragma unroll
      for (int nt = 0; nt < 4; nt++) {
        uint32_t bb[4];
        const int g16 = pg * 8 + nt * 2 + lhalf;
        ldsm4t(bb, rowb + ((g16 ^ kx) << 4));
        mma16816(o[0][nt * 2 + 0], ap[0], bb + 0);
        mma16816(o[0][nt * 2 + 1], ap[0], bb + 2);
        mma16816(o[1][nt * 2 + 0], ap[1], bb + 0);
        mma16816(o[1][nt * 2 + 1], ap[1], bb + 2);
      }
    }
    __syncthreads();  // V-buf free

    if (kt + 2 < NCH) load_v(kt + 2, kt & 1);
    cp_commit();
  }

  // ---- l combine across key halves via smem ----
  lac0 += __shfl_xor_sync(0xffffffffu, lac0, 1);
  lac0 += __shfl_xor_sync(0xffffffffu, lac0, 2);
  lac1 += __shfl_xor_sync(0xffffffffu, lac1, 1);
  lac1 += __shfl_xor_sync(0xffffffffu, lac1, 2);
  if ((lane & 3) == 0) {
    asm volatile("st.shared.f32 [%0], %1;" :: "r"(smb + SM_L + (kh * 128 + r0l) * 4), "f"(lac0) : "memory");
    asm volatile("st.shared.f32 [%0], %1;" :: "r"(smb + SM_L + (kh * 128 + r0l + 8) * 4), "f"(lac1) : "memory");
  }
  __syncthreads();

#pragma unroll
  for (int mt = 0; mt < 2; mt++) {
    const int lr0 = pr * 32 + mt * 16 + rowa;  // local rows lr0, lr0+8
    float la0, lb0, la1, lb1;
    asm volatile("ld.shared.f32 %0, [%1];" : "=f"(la0) : "r"(smb + SM_L + lr0 * 4));
    asm volatile("ld.shared.f32 %0, [%1];" : "=f"(lb0) : "r"(smb + SM_L + (128 + lr0) * 4));
    asm volatile("ld.shared.f32 %0, [%1];" : "=f"(la1) : "r"(smb + SM_L + (lr0 + 8) * 4));
    asm volatile("ld.shared.f32 %0, [%1];" : "=f"(lb1) : "r"(smb + SM_L + (128 + lr0 + 8) * 4));
    const float inv0 = 1.0f / (la0 + lb0), inv1 = 1.0f / (la1 + lb1);
    float* o0 = out + ((size_t)b * kSQ + q0 + lr0) * kDV + pg * 64;
    float* o1 = o0 + (size_t)8 * kDV;
#pragma unroll
    for (int nt = 0; nt < 8; nt++) {
      const int c = nt * 8 + colq;
      float2 w0, w1;
      w0.x = o[mt][nt][0] * inv0;
      w0.y = o[mt][nt][1] * inv0;
      w1.x = o[mt][nt][2] * inv1;
      w1.y = o[mt][nt][3] * inv1;
      *reinterpret_cast<float2*>(o0 + c) = w0;
      *reinterpret_cast<float2*>(o1 + c) = w1;
    }
  }
}

extern "C" void kernel_launch(void* const* d_in, const int* in_sizes, int n_in,
                              void* d_out, int out_size) {
  const float* q = (const float*)d_in[0];
  const float* k = (const float*)d_in[1];
  const float* v = (const float*)d_in[2];
  const int* mask = (const int*)d_in[3];
  const float* du = (const float*)d_in[4];
  float* out = (float*)d_out;

  convert_all<<<(int)(((size_t)kB * kSQ * kD / 8 + 255) / 256), 256>>>(q, k, v);
  make_dropbits<<<(int)((size_t)kB * kSQ * kSK / 1024 / 8), 256>>>(du);
  make_maskbits<<<8, 256>>>(mask);

  cudaFuncSetAttribute(attn_hmma_kernel, cudaFuncAttributeMaxDynamicSharedMemorySize,
                       (int)SM_BYTES);
  attn_hmma_kernel<<<dim3(kSQ / BQ, kB), NT, SM_BYTES>>>(out);
}

// round 8
// speedup vs baseline: 6.7313x; 1.0199x over previous
#include <cuda_runtime.h>
#include <cuda_fp16.h>
#include <stdint.h>

namespace {
constexpr int kB = 64, kSQ = 1024, kSK = 1024, kD = 256, kDV = 256;
constexpr int BQ = 128, BKC = 64, NCH = kSK / BKC, NT = 512;
constexpr float kDropP = 0.1f, kKeepInv = 1.0f / 0.9f;

constexpr uint32_t SM_Q = 0;         // 128 x 512B = 64KB
constexpr uint32_t SM_K = 65536;     // 2 x (64 x 512B) = 64KB
constexpr uint32_t SM_V = 131072;    // 2 x (64 x 512B) = 64KB
constexpr uint32_t SM_P = 196608;    // 128 rows x 128B = 16KB
constexpr uint32_t SM_L = 212992;    // float[2][128] = 1KB
constexpr uint32_t SM_BYTES = 214016 + 1024;

__device__ __forceinline__ uint32_t swz(int row, int g) {  // 512B rows
  return (uint32_t)(row * 512 + ((g ^ (row & 7)) << 4));
}
__device__ __forceinline__ void cpa16(uint32_t d, const void* s) {
  asm volatile("cp.async.cg.shared.global [%0], [%1], 16;" :: "r"(d), "l"(s));
}
__device__ __forceinline__ void cp_commit() { asm volatile("cp.async.commit_group;" ::: "memory"); }
__device__ __forceinline__ void cp_wait2() { asm volatile("cp.async.wait_group 2;" ::: "memory"); }

__device__ __forceinline__ void ldsm4(uint32_t* r, uint32_t a) {
  asm volatile("ldmatrix.sync.aligned.m8n8.x4.shared.b16 {%0,%1,%2,%3}, [%4];"
               : "=r"(r[0]), "=r"(r[1]), "=r"(r[2]), "=r"(r[3]) : "r"(a));
}
__device__ __forceinline__ void ldsm4t(uint32_t* r, uint32_t a) {
  asm volatile("ldmatrix.sync.aligned.m8n8.x4.trans.shared.b16 {%0,%1,%2,%3}, [%4];"
               : "=r"(r[0]), "=r"(r[1]), "=r"(r[2]), "=r"(r[3]) : "r"(a));
}
__device__ __forceinline__ void mma16816(float* d, const uint32_t* a, const uint32_t* b) {
  asm volatile(
      "mma.sync.aligned.m16n8k16.row.col.f32.f16.f16.f32 "
      "{%0,%1,%2,%3}, {%4,%5,%6,%7}, {%8,%9}, {%0,%1,%2,%3};"
      : "+f"(d[0]), "+f"(d[1]), "+f"(d[2]), "+f"(d[3])
      : "r"(a[0]), "r"(a[1]), "r"(a[2]), "r"(a[3]), "r"(b[0]), "r"(b[1]));
}
}  // namespace

__device__ __half g_Qh[(size_t)kB * kSQ * kD];   // Q * 2^-4
__device__ __half g_Kh[(size_t)kB * kSK * kD];
__device__ __half g_Vh[(size_t)kB * kSK * kDV];
__device__ uint32_t g_dropbits[(size_t)kB * kSQ * (kSK / 32)];  // 8MB
__device__ uint32_t g_maskbits[kB * (kSK / 32)];                // 8KB

__global__ void prep_fused(const float* __restrict__ q, const float* __restrict__ k,
                           const float* __restrict__ v, const float* __restrict__ du,
                           const int* __restrict__ mask) {
  constexpr int nConv = (int)((size_t)kB * kSQ * kD / 8 / 256);          // 8192
  constexpr int nDrop = (int)((size_t)kB * kSQ * kSK / 1024 / 8);        // 8192
  const int bx = blockIdx.x;
  if (bx < nConv) {
    const size_t base = ((size_t)bx * 256 + threadIdx.x) * 8;
    {
      float4 x0 = *reinterpret_cast<const float4*>(q + base);
      float4 x1 = *reinterpret_cast<const float4*>(q + base + 4);
      __half2* o = reinterpret_cast<__half2*>(g_Qh + base);
      o[0] = __floats2half2_rn(x0.x * 0.0625f, x0.y * 0.0625f);
      o[1] = __floats2half2_rn(x0.z * 0.0625f, x0.w * 0.0625f);
      o[2] = __floats2half2_rn(x1.x * 0.0625f, x1.y * 0.0625f);
      o[3] = __floats2half2_rn(x1.z * 0.0625f, x1.w * 0.0625f);
    }
    {
      float4 x0 = *reinterpret_cast<const float4*>(k + base);
      float4 x1 = *reinterpret_cast<const float4*>(k + base + 4);
      __half2* o = reinterpret_cast<__half2*>(g_Kh + base);
      o[0] = __floats2half2_rn(x0.x, x0.y);
      o[1] = __floats2half2_rn(x0.z, x0.w);
      o[2] = __floats2half2_rn(x1.x, x1.y);
      o[3] = __floats2half2_rn(x1.z, x1.w);
    }
    {
      float4 x0 = *reinterpret_cast<const float4*>(v + base);
      float4 x1 = *reinterpret_cast<const float4*>(v + base + 4);
      __half2* o = reinterpret_cast<__half2*>(g_Vh + base);
      o[0] = __floats2half2_rn(x0.x, x0.y);
      o[1] = __floats2half2_rn(x0.z, x0.w);
      o[2] = __floats2half2_rn(x1.x, x1.y);
      o[3] = __floats2half2_rn(x1.z, x1.w);
    }
  } else if (bx < nConv + nDrop) {
    const int lane = threadIdx.x & 31;
    const size_t warp = (((size_t)(bx - nConv) * 256) + threadIdx.x) >> 5;
    const size_t base = warp * 1024;
    uint32_t myword = 0;
#pragma unroll
    for (int i = 0; i < 32; i++) {
      const float u = du[base + (size_t)i * 32 + lane];
      const uint32_t bm = __ballot_sync(0xffffffffu, u >= kDropP);
      if (lane == i) myword = bm;
    }
    g_dropbits[warp * 32 + lane] = myword;
  } else {
    const int lane = threadIdx.x & 31;
    const int warp = (int)((((bx - nConv - nDrop) * 256) + threadIdx.x) >> 5);
    const size_t base = (size_t)warp * 1024;
    uint32_t myword = 0;
#pragma unroll
    for (int i = 0; i < 32; i++) {
      const int m = mask[base + (size_t)i * 32 + lane];
      const uint32_t bm = __ballot_sync(0xffffffffu, m != 0);
      if (lane == i) myword = bm;
    }
    g_maskbits[warp * 32 + lane] = myword;
  }
}

__global__ __launch_bounds__(NT, 1)
void attn_hmma_kernel(float* __restrict__ out) {
  extern __shared__ char smraw[];
  uint32_t smb = (uint32_t)__cvta_generic_to_shared(smraw);
  smb = (smb + 1023u) & ~1023u;
  const int tid = threadIdx.x, wid = tid >> 5, lane = tid & 31;
  const int b = blockIdx.y, q0 = blockIdx.x * BQ;
  const int g = wid & 7;    // QK row group (16 rows)
  const int kh = wid >> 3;  // QK key half (32 keys)
  const int pr = wid >> 2;  // PV row group (32 rows)
  const int pg = wid & 3;   // PV col group (64 cols)

  auto load_q = [&]() {
#pragma unroll
    for (int u = 0; u < 8; u++) {
      const int idx = tid + u * NT, row = idx >> 5, gr = idx & 31;
      cpa16(smb + SM_Q + swz(row, gr), g_Qh + ((size_t)(b * kSQ + q0 + row)) * kD + gr * 8);
    }
  };
  auto load_k = [&](int c, int buf) {
#pragma unroll
    for (int u = 0; u < 4; u++) {
      const int idx = tid + u * NT, row = idx >> 5, gr = idx & 31;
      cpa16(smb + SM_K + buf * 32768 + swz(row, gr),
            g_Kh + ((size_t)(b * kSK + c * BKC + row)) * kD + gr * 8);
    }
  };
  auto load_v = [&](int c, int buf) {
#pragma unroll
    for (int u = 0; u < 4; u++) {
      const int idx = tid + u * NT, row = idx >> 5, gr = idx & 31;
      cpa16(smb + SM_V + buf * 32768 + swz(row, gr),
            g_Vh + ((size_t)(b * kSK + c * BKC + row)) * kDV + gr * 8);
    }
  };

  load_q(); load_k(0, 0); load_v(0, 0); cp_commit();  // G1
  load_k(1, 1); cp_commit();                          // G2
  load_v(1, 1); cp_commit();                          // G3

  // ---- lane constants ----
  const int lq = lane & 15, lhalf = lane >> 4;
  const int x7q = lq & 7;                    // row&7 for Q/P/V ldsm rows
  const int x7k = lane & 7;                  // row&7 for K ldsm rows
  const int rowa = lane >> 2, colq = (lane & 3) * 2;
  const int r0l = g * 16 + rowa;
  const uint32_t qbase = smb + SM_Q + (g * 16 + lq) * 512;
  const int krow_off = (lane & 7) + ((lane >> 4) << 3);
  const int kg_half = (lane >> 3) & 1;
  const uint32_t pb0 = smb + SM_P + (pr * 32 + lq) * 128;       // PV a mt=0
  const uint32_t pb1 = pb0 + 16 * 128;                          // PV a mt=1
  uint32_t voff[4];
#pragma unroll
  for (int nt = 0; nt < 4; nt++) voff[nt] = (uint32_t)(((pg * 8 + nt * 2 + lhalf) ^ x7q) << 4);
  const uint32_t pst0 = smb + SM_P + r0l * 128 + (lane & 3) * 4;
  const uint32_t pst1 = pst0 + 8 * 128;

  const int grow0 = q0 + r0l;

  float o[2][8][4];
#pragma unroll
  for (int mt = 0; mt < 2; mt++)
#pragma unroll
    for (int nt = 0; nt < 8; nt++)
#pragma unroll
      for (int e = 0; e < 4; e++) o[mt][nt][e] = 0.f;
  float lac0 = 0.f, lac1 = 0.f;

  for (int kt = 0; kt < NCH; kt++) {
    cp_wait2();
    __syncthreads();  // K/V(kt) resident; P(kt-1) consumed
    const uint32_t kbuf = smb + SM_K + (kt & 1) * 32768;
    const uint32_t vbuf = smb + SM_V + (kt & 1) * 32768;

    // hoisted bit-words (hidden under QK)
    const int wix = kt * 2 + kh;
    const uint32_t mword = g_maskbits[b * 32 + wix];
    const uint32_t dw0 = g_dropbits[(size_t)(b * kSQ + grow0) * 32 + wix];
    const uint32_t dw1 = g_dropbits[(size_t)(b * kSQ + grow0 + 8) * 32 + wix];

    // ---- QK: 16 rows x 32 keys, software-pipelined frags ----
    float s[4][4];
#pragma unroll
    for (int t = 0; t < 4; t++) { s[t][0] = s[t][1] = s[t][2] = s[t][3] = 0.f; }

    const uint32_t kb0 = kbuf + (kh * 32 + krow_off) * 512;  // j=0 base
    uint32_t acur[4], bcur[8], anxt[4], bnxt[8];
    ldsm4(acur, qbase + ((lhalf ^ x7q) << 4));
    {
      const uint32_t bo = (uint32_t)((kg_half ^ x7k) << 4);
      ldsm4(bcur, kb0 + bo);
      ldsm4(bcur + 4, kb0 + 8192 + bo);
    }
#pragma unroll
    for (int ds = 0; ds < 16; ds++) {
      if (ds < 15) {
        ldsm4(anxt, qbase + (((((ds + 1) << 1) + lhalf) ^ x7q) << 4));
        const uint32_t bo = (uint32_t)(((((ds + 1) << 1) + kg_half) ^ x7k) << 4);
        ldsm4(bnxt, kb0 + bo);
        ldsm4(bnxt + 4, kb0 + 8192 + bo);
      }
      mma16816(s[0], acur, bcur + 0);
      mma16816(s[1], acur, bcur + 2);
      mma16816(s[2], acur, bcur + 4);
      mma16816(s[3], acur, bcur + 6);
      if (ds < 15) {
#pragma unroll
        for (int e = 0; e < 4; e++) acur[e] = anxt[e];
#pragma unroll
        for (int e = 0; e < 8; e++) bcur[e] = bnxt[e];
      }
    }

    // ---- mask/exp/dropout via bitwords; write P fp16 to smem ----
#pragma unroll
    for (int t = 0; t < 4; t++) {
      const int bp = t * 8 + colq;
      const bool m0 = (mword >> bp) & 1u, m1 = (mword >> (bp + 1)) & 1u;
      float p0 = m0 ? __expf(s[t][0]) : 0.f;
      float p1 = m1 ? __expf(s[t][1]) : 0.f;
      float p2 = m0 ? __expf(s[t][2]) : 0.f;
      float p3 = m1 ? __expf(s[t][3]) : 0.f;
      lac0 += p0 + p1;
      lac1 += p2 + p3;
      p0 *= ((dw0 >> bp) & 1u) ? kKeepInv : 0.f;
      p1 *= ((dw0 >> (bp + 1)) & 1u) ? kKeepInv : 0.f;
      p2 *= ((dw1 >> bp) & 1u) ? kKeepInv : 0.f;
      p3 *= ((dw1 >> (bp + 1)) & 1u) ? kKeepInv : 0.f;
      __half2 ha = __floats2half2_rn(p0, p1), hb = __floats2half2_rn(p2, p3);
      const int grp = kh * 4 + t;
      const uint32_t xo = (uint32_t)((grp ^ rowa) << 4);
      asm volatile("st.shared.b32 [%0], %1;" :: "r"(pst0 + xo), "r"(*reinterpret_cast<uint32_t*>(&ha)) : "memory");
      asm volatile("st.shared.b32 [%0], %1;" :: "r"(pst1 + xo), "r"(*reinterpret_cast<uint32_t*>(&hb)) : "memory");
    }
    __syncthreads();  // P(kt) visible; K-buf free

    if (kt + 2 < NCH) load_k(kt + 2, kt & 1);
    cp_commit();

    // ---- PV: 32 rows x 64 dv, pipelined frags ----
    uint32_t ap0[4], ap1[4], apn0[4], apn1[4], bc[4], bn[4];
    ldsm4(ap0, pb0 + ((lhalf ^ x7q) << 4));
    ldsm4(ap1, pb1 + ((lhalf ^ x7q) << 4));
    ldsm4t(bc, vbuf + lq * 512 + voff[0]);
#pragma unroll
    for (int ks = 0; ks < 4; ks++) {
      const uint32_t vb = vbuf + (ks * 16 + lq) * 512;
#pragma unroll
      for (int nt = 0; nt < 4; nt++) {
        if (nt < 3) {
          ldsm4t(bn, vb + voff[nt + 1]);
        } else if (ks < 3) {
          ldsm4t(bn, vbuf + ((ks + 1) * 16 + lq) * 512 + voff[0]);
        }
        if (nt == 2 && ks < 3) {
          const uint32_t po = (uint32_t)(((((ks + 1) << 1) + lhalf) ^ x7q) << 4);
          ldsm4(apn0, pb0 + po);
          ldsm4(apn1, pb1 + po);
        }
        mma16816(o[0][nt * 2 + 0], ap0, bc + 0);
        mma16816(o[0][nt * 2 + 1], ap0, bc + 2);
        mma16816(o[1][nt * 2 + 0], ap1, bc + 0);
        mma16816(o[1][nt * 2 + 1], ap1, bc + 2);
        if (nt < 3 || ks < 3) {
#pragma unroll
          for (int e = 0; e < 4; e++) bc[e] = bn[e];
        }
      }
      if (ks < 3) {
#pragma unroll
        for (int e = 0; e < 4; e++) { ap0[e] = apn0[e]; ap1[e] = apn1[e]; }
      }
    }
    __syncthreads();  // V-buf free

    if (kt + 2 < NCH) load_v(kt + 2, kt & 1);
    cp_commit();
  }

  // ---- l combine across key halves via smem ----
  lac0 += __shfl_xor_sync(0xffffffffu, lac0, 1);
  lac0 += __shfl_xor_sync(0xffffffffu, lac0, 2);
  lac1 += __shfl_xor_sync(0xffffffffu, lac1, 1);
  lac1 += __shfl_xor_sync(0xffffffffu, lac1, 2);
  if ((lane & 3) == 0) {
    asm volatile("st.shared.f32 [%0], %1;" :: "r"(smb + SM_L + (kh * 128 + r0l) * 4), "f"(lac0) : "memory");
    asm volatile("st.shared.f32 [%0], %1;" :: "r"(smb + SM_L + (kh * 128 + r0l + 8) * 4), "f"(lac1) : "memory");
  }
  __syncthreads();

#pragma unroll
  for (int mt = 0; mt < 2; mt++) {
    const int lr0 = pr * 32 + mt * 16 + rowa;  // local rows lr0, lr0+8
    float la0, lb0, la1, lb1;
    asm volatile("ld.shared.f32 %0, [%1];" : "=f"(la0) : "r"(smb + SM_L + lr0 * 4));
    asm volatile("ld.shared.f32 %0, [%1];" : "=f"(lb0) : "r"(smb + SM_L + (128 + lr0) * 4));
    asm volatile("ld.shared.f32 %0, [%1];" : "=f"(la1) : "r"(smb + SM_L + (lr0 + 8) * 4));
    asm volatile("ld.shared.f32 %0, [%1];" : "=f"(lb1) : "r"(smb + SM_L + (128 + lr0 + 8) * 4));
    const float inv0 = 1.0f / (la0 + lb0), inv1 = 1.0f / (la1 + lb1);
    float* o0 = out + ((size_t)b * kSQ + q0 + lr0) * kDV + pg * 64;
    float* o1 = o0 + (size_t)8 * kDV;
#pragma unroll
    for (int nt = 0; nt < 8; nt++) {
      const int c = nt * 8 + colq;
      float2 w0, w1;
      w0.x = o[mt][nt][0] * inv0;
      w0.y = o[mt][nt][1] * inv0;
      w1.x = o[mt][nt][2] * inv1;
      w1.y = o[mt][nt][3] * inv1;
      *reinterpret_cast<float2*>(o0 + c) = w0;
      *reinterpret_cast<float2*>(o1 + c) = w1;
    }
  }
}

extern "C" void kernel_launch(void* const* d_in, const int* in_sizes, int n_in,
                              void* d_out, int out_size) {
  const float* q = (const float*)d_in[0];
  const float* k = (const float*)d_in[1];
  const float* v = (const float*)d_in[2];
  const int* mask = (const int*)d_in[3];
  const float* du = (const float*)d_in[4];
  float* out = (float*)d_out;

  constexpr int nConv = (int)((size_t)kB * kSQ * kD / 8 / 256);
  constexpr int nDrop = (int)((size_t)kB * kSQ * kSK / 1024 / 8);
  prep_fused<<<nConv + nDrop + 8, 256>>>(q, k, v, du, mask);

  cudaFuncSetAttribute(attn_hmma_kernel, cudaFuncAttributeMaxDynamicSharedMemorySize,
                       (int)SM_BYTES);
  attn_hmma_kernel<<<dim3(kSQ / BQ, kB), NT, SM_BYTES>>>(out);
}